// round 1
// baseline (speedup 1.0000x reference)
#include <cuda_runtime.h>
#include <math.h>

// ---------------------------------------------------------------------------
// TransformerBlock: B=16, N=1024, C=384, H=6, D=64, HID=1536
// fp32 baseline: fused LN, register-blocked SGEMM w/ fused epilogues,
// flash-style attention.
// ---------------------------------------------------------------------------

#define NTOK   16384      // B*N
#define EMBED  384
#define HEADS  6
#define HEAD_DIM 64
#define MLPHID 1536
#define QKVN   1152       // 3*EMBED

// Scratch (device globals; no allocation allowed)
__device__ float g_h   [NTOK * EMBED];   // LN output (reused for both LNs)
__device__ float g_qkv [NTOK * QKVN];
__device__ float g_ctx [NTOK * EMBED];
__device__ float g_x1  [NTOK * EMBED];
__device__ float g_mlp [NTOK * MLPHID];

// ---------------------------------------------------------------------------
// LayerNorm: one block (384 threads) per row
// ---------------------------------------------------------------------------
__global__ void ln_kernel(const float* __restrict__ x,
                          const float* __restrict__ g,
                          const float* __restrict__ b,
                          float* __restrict__ out)
{
    int row = blockIdx.x;
    int tid = threadIdx.x;              // 0..383
    float v = x[row * EMBED + tid];
    float s = v, sq = v * v;
    #pragma unroll
    for (int m = 16; m; m >>= 1) {
        s  += __shfl_xor_sync(0xffffffffu, s,  m);
        sq += __shfl_xor_sync(0xffffffffu, sq, m);
    }
    __shared__ float ss[12], ssq[12];
    int w = tid >> 5, l = tid & 31;
    if (l == 0) { ss[w] = s; ssq[w] = sq; }
    __syncthreads();
    if (w == 0) {
        float a  = (l < 12) ? ss[l]  : 0.0f;
        float aq = (l < 12) ? ssq[l] : 0.0f;
        #pragma unroll
        for (int m = 16; m; m >>= 1) {
            a  += __shfl_xor_sync(0xffffffffu, a,  m);
            aq += __shfl_xor_sync(0xffffffffu, aq, m);
        }
        if (l == 0) { ss[0] = a; ssq[0] = aq; }
    }
    __syncthreads();
    float mean = ss[0] * (1.0f / EMBED);
    float var  = ssq[0] * (1.0f / EMBED) - mean * mean;
    float inv  = rsqrtf(var + 1e-5f);
    out[row * EMBED + tid] = (v - mean) * inv * g[tid] + b[tid];
}

// ---------------------------------------------------------------------------
// SGEMM: C[M,N] = A[M,K] @ B[K,N] (+bias, +resid, gelu)   all row-major
// BM=BN=128, BK=8, 256 threads, 8x8 per thread. M,N multiples of 128,
// K multiple of 8 (all true for this problem).
// ---------------------------------------------------------------------------
#define EPI_BIAS       0
#define EPI_BIAS_RESID 1
#define EPI_BIAS_GELU  2

template <int EPI>
__global__ __launch_bounds__(256)
void sgemm_kernel(const float* __restrict__ A, const float* __restrict__ B,
                  const float* __restrict__ bias, const float* __restrict__ resid,
                  float* __restrict__ C, int M, int N, int K)
{
    const int BM = 128, BN = 128, BK = 8, TM = 8, TN = 8;
    __shared__ float As[BK][BM];
    __shared__ float Bs[BK][BN];

    int tid = threadIdx.x;
    int tx = tid & 15;          // 0..15  -> col group
    int ty = tid >> 4;          // 0..15  -> row group
    int rowBase = blockIdx.y * BM;
    int colBase = blockIdx.x * BN;

    const float* Ap = A + (size_t)rowBase * K;
    const float* Bp = B + colBase;

    int aRow = tid >> 1;        // 0..127
    int aCol = (tid & 1) * 4;   // 0 or 4
    int bRow = tid >> 5;        // 0..7
    int bCol = (tid & 31) * 4;  // 0..124

    float acc[TM][TN] = {};

    for (int k0 = 0; k0 < K; k0 += BK) {
        float4 av = *reinterpret_cast<const float4*>(Ap + (size_t)aRow * K + k0 + aCol);
        As[aCol + 0][aRow] = av.x;
        As[aCol + 1][aRow] = av.y;
        As[aCol + 2][aRow] = av.z;
        As[aCol + 3][aRow] = av.w;
        float4 bv = *reinterpret_cast<const float4*>(Bp + (size_t)(k0 + bRow) * N + bCol);
        *reinterpret_cast<float4*>(&Bs[bRow][bCol]) = bv;
        __syncthreads();

        #pragma unroll
        for (int k = 0; k < BK; k++) {
            float rm[TM], rn[TN];
            #pragma unroll
            for (int i = 0; i < TM; i++) rm[i] = As[k][ty * TM + i];
            #pragma unroll
            for (int j = 0; j < TN; j++) rn[j] = Bs[k][tx * TN + j];
            #pragma unroll
            for (int i = 0; i < TM; i++)
                #pragma unroll
                for (int j = 0; j < TN; j++)
                    acc[i][j] += rm[i] * rn[j];
        }
        __syncthreads();
    }

    // Epilogue
    #pragma unroll
    for (int i = 0; i < TM; i++) {
        int row = rowBase + ty * TM + i;
        #pragma unroll
        for (int j = 0; j < TN; j++) {
            int col = colBase + tx * TN + j;
            float v = acc[i][j] + bias[col];
            if (EPI == EPI_BIAS_GELU) {
                v = 0.5f * v * (1.0f + erff(v * 0.70710678118654752f));
            }
            if (EPI == EPI_BIAS_RESID) {
                v += resid[(size_t)row * N + col];
            }
            C[(size_t)row * N + col] = v;
        }
    }
}

// ---------------------------------------------------------------------------
// Flash attention: grid (16 q-tiles, 96 b*h), 128 threads.
// Br=Bc=64, d=64. smem: Q^T (k-major) + K^T (k-major, reused as P) + V = 48KB.
// Thread layout: rg = tid/16 owns rows rg*8..+7; cg = tid%16 owns cols cg*4..+3.
// ---------------------------------------------------------------------------
__global__ __launch_bounds__(128)
void attn_kernel(const float* __restrict__ qkv, float* __restrict__ ctx)
{
    __shared__ float Qs[64 * 64];   // [k][r]
    __shared__ float KP[64 * 64];   // K as [k][n], later P as [r][j]
    __shared__ float Vs[64 * 64];   // [j][c]

    int tid = threadIdx.x;
    int rg = tid >> 4;              // 0..7
    int cg = tid & 15;              // 0..15
    int qt = blockIdx.x;            // 0..15
    int bh = blockIdx.y;            // 0..95
    int b  = bh / HEADS;
    int h  = bh % HEADS;

    const size_t tokBase = (size_t)b * 1024;
    const int qOff = h * HEAD_DIM;          // q cols in qkv row
    const int kOff = EMBED + h * HEAD_DIM;  // k cols
    const int vOff = 2 * EMBED + h * HEAD_DIM;

    // Load Q tile transposed: Qs[k][r]
    #pragma unroll
    for (int it = 0; it < 8; it++) {
        int lin = it * 128 + tid;           // 0..1023 float4s
        int r = lin >> 4;                   // 0..63
        int c4 = (lin & 15) * 4;            // 0..60
        float4 q = *reinterpret_cast<const float4*>(
            qkv + (tokBase + qt * 64 + r) * QKVN + qOff + c4);
        Qs[(c4 + 0) * 64 + r] = q.x;
        Qs[(c4 + 1) * 64 + r] = q.y;
        Qs[(c4 + 2) * 64 + r] = q.z;
        Qs[(c4 + 3) * 64 + r] = q.w;
    }

    float m[8], l[8], O[8][4];
    #pragma unroll
    for (int i = 0; i < 8; i++) {
        m[i] = -1e30f; l[i] = 0.0f;
        #pragma unroll
        for (int c = 0; c < 4; c++) O[i][c] = 0.0f;
    }

    for (int t = 0; t < 16; t++) {
        __syncthreads();   // previous O-gemm done reading KP/Vs
        // Load K tile transposed (KP[k][n]) and V tile direct (Vs[j][c])
        #pragma unroll
        for (int it = 0; it < 8; it++) {
            int lin = it * 128 + tid;
            int r = lin >> 4;
            int c4 = (lin & 15) * 4;
            const float* rowp = qkv + (tokBase + t * 64 + r) * QKVN;
            float4 kv = *reinterpret_cast<const float4*>(rowp + kOff + c4);
            KP[(c4 + 0) * 64 + r] = kv.x;
            KP[(c4 + 1) * 64 + r] = kv.y;
            KP[(c4 + 2) * 64 + r] = kv.z;
            KP[(c4 + 3) * 64 + r] = kv.w;
            float4 vv = *reinterpret_cast<const float4*>(rowp + vOff + c4);
            *reinterpret_cast<float4*>(&Vs[r * 64 + c4]) = vv;
        }
        __syncthreads();

        // S = Q @ K^T  (64x64), thread owns 8x4
        float s[8][4] = {};
        #pragma unroll 4
        for (int k = 0; k < 64; k++) {
            float rq[8], rk[4];
            #pragma unroll
            for (int i = 0; i < 8; i++) rq[i] = Qs[k * 64 + rg * 8 + i];
            #pragma unroll
            for (int j = 0; j < 4; j++) rk[j] = KP[k * 64 + cg * 4 + j];
            #pragma unroll
            for (int i = 0; i < 8; i++)
                #pragma unroll
                for (int j = 0; j < 4; j++)
                    s[i][j] += rq[i] * rk[j];
        }

        // online softmax update (scale = 1/sqrt(64) = 0.125)
        #pragma unroll
        for (int i = 0; i < 8; i++) {
            float mt = -1e30f;
            #pragma unroll
            for (int j = 0; j < 4; j++) {
                s[i][j] *= 0.125f;
                mt = fmaxf(mt, s[i][j]);
            }
            #pragma unroll
            for (int mm = 8; mm; mm >>= 1)
                mt = fmaxf(mt, __shfl_xor_sync(0xffffffffu, mt, mm));
            float mn = fmaxf(m[i], mt);
            float al = __expf(m[i] - mn);
            m[i] = mn;
            float ps = 0.0f;
            #pragma unroll
            for (int j = 0; j < 4; j++) {
                s[i][j] = __expf(s[i][j] - mn);
                ps += s[i][j];
            }
            #pragma unroll
            for (int mm = 8; mm; mm >>= 1)
                ps += __shfl_xor_sync(0xffffffffu, ps, mm);
            l[i] = l[i] * al + ps;
            #pragma unroll
            for (int c = 0; c < 4; c++) O[i][c] *= al;
        }

        __syncthreads();   // all threads done reading KP (K) before P overwrite
        // write P into KP as [r][j]
        #pragma unroll
        for (int i = 0; i < 8; i++)
            #pragma unroll
            for (int j = 0; j < 4; j++)
                KP[(rg * 8 + i) * 64 + cg * 4 + j] = s[i][j];
        __syncthreads();

        // O += P @ V
        #pragma unroll 4
        for (int j = 0; j < 64; j++) {
            float rp[8], rv[4];
            #pragma unroll
            for (int i = 0; i < 8; i++) rp[i] = KP[(rg * 8 + i) * 64 + j];
            #pragma unroll
            for (int c = 0; c < 4; c++) rv[c] = Vs[j * 64 + cg * 4 + c];
            #pragma unroll
            for (int i = 0; i < 8; i++)
                #pragma unroll
                for (int c = 0; c < 4; c++)
                    O[i][c] += rp[i] * rv[c];
        }
    }

    // normalize and write ctx (B,N,C layout)
    #pragma unroll
    for (int i = 0; i < 8; i++) {
        float inv = 1.0f / l[i];
        size_t row = tokBase + qt * 64 + rg * 8 + i;
        float4 o;
        o.x = O[i][0] * inv; o.y = O[i][1] * inv;
        o.z = O[i][2] * inv; o.w = O[i][3] * inv;
        *reinterpret_cast<float4*>(ctx + row * EMBED + h * HEAD_DIM + cg * 4) = o;
    }
}

// ---------------------------------------------------------------------------
// Launch
// ---------------------------------------------------------------------------
extern "C" void kernel_launch(void* const* d_in, const int* in_sizes, int n_in,
                              void* d_out, int out_size)
{
    const float* x      = (const float*)d_in[0];
    const float* n1g    = (const float*)d_in[1];
    const float* n1b    = (const float*)d_in[2];
    const float* qkv_w  = (const float*)d_in[3];
    const float* qkv_b  = (const float*)d_in[4];
    const float* proj_w = (const float*)d_in[5];
    const float* proj_b = (const float*)d_in[6];
    const float* n2g    = (const float*)d_in[7];
    const float* n2b    = (const float*)d_in[8];
    const float* fc1_w  = (const float*)d_in[9];
    const float* fc1_b  = (const float*)d_in[10];
    const float* fc2_w  = (const float*)d_in[11];
    const float* fc2_b  = (const float*)d_in[12];
    float* out = (float*)d_out;

    float *h, *qkv, *ctx, *x1, *mlp;
    cudaGetSymbolAddress((void**)&h,   g_h);
    cudaGetSymbolAddress((void**)&qkv, g_qkv);
    cudaGetSymbolAddress((void**)&ctx, g_ctx);
    cudaGetSymbolAddress((void**)&x1,  g_x1);
    cudaGetSymbolAddress((void**)&mlp, g_mlp);

    // 1) h = LN1(x)
    ln_kernel<<<NTOK, EMBED>>>(x, n1g, n1b, h);

    // 2) qkv = h @ qkv_w + qkv_b
    sgemm_kernel<EPI_BIAS><<<dim3(QKVN / 128, NTOK / 128), 256>>>(
        h, qkv_w, qkv_b, nullptr, qkv, NTOK, QKVN, EMBED);

    // 3) attention -> ctx
    attn_kernel<<<dim3(16, 96), 128>>>(qkv, ctx);

    // 4) x1 = x + ctx @ proj_w + proj_b
    sgemm_kernel<EPI_BIAS_RESID><<<dim3(EMBED / 128, NTOK / 128), 256>>>(
        ctx, proj_w, proj_b, x, x1, NTOK, EMBED, EMBED);

    // 5) h = LN2(x1)
    ln_kernel<<<NTOK, EMBED>>>(x1, n2g, n2b, h);

    // 6) mlp = gelu(h @ fc1_w + fc1_b)
    sgemm_kernel<EPI_BIAS_GELU><<<dim3(MLPHID / 128, NTOK / 128), 256>>>(
        h, fc1_w, fc1_b, nullptr, mlp, NTOK, MLPHID, EMBED);

    // 7) out = x1 + mlp @ fc2_w + fc2_b
    sgemm_kernel<EPI_BIAS_RESID><<<dim3(EMBED / 128, NTOK / 128), 256>>>(
        mlp, fc2_w, fc2_b, x1, out, NTOK, EMBED, MLPHID);
}

// round 3
// speedup vs baseline: 1.8370x; 1.8370x over previous
#include <cuda_runtime.h>
#include <cstdint>
#include <math.h>

// ---------------------------------------------------------------------------
// TransformerBlock: B=16, N=1024, C=384, H=6, D=64, HID=1536
// Round 3: mma.sync tf32 GEMMs (compute_100-portable tensor path),
// cp.async 3-stage pipeline, fused epilogues. fp32 attention + LN.
// ---------------------------------------------------------------------------

#define NTOK   16384
#define EMBED  384
#define HEADS  6
#define HEAD_DIM 64
#define MLPHID 1536
#define QKVN   1152

__device__ float g_h   [NTOK * EMBED];
__device__ float g_qkv [NTOK * QKVN];
__device__ float g_ctx [NTOK * EMBED];
__device__ float g_x1  [NTOK * EMBED];
__device__ float g_mlp [NTOK * MLPHID];
__device__ float g_wt  [QKVN*EMBED + EMBED*EMBED + MLPHID*EMBED + EMBED*MLPHID];

// ---------------------------------------------------------------------------
__device__ __forceinline__ uint32_t smem_u32(const void* p) {
    uint32_t a;
    asm("{ .reg .u64 t; cvta.to.shared.u64 t, %1; cvt.u32.u64 %0, t; }" : "=r"(a) : "l"(p));
    return a;
}
__device__ __forceinline__ float tf32r(float x) {
    uint32_t u;
    asm("cvt.rna.tf32.f32 %0, %1;" : "=r"(u) : "f"(x));
    return __uint_as_float(u);
}
__device__ __forceinline__ void cp_async16(uint32_t saddr, const void* gptr) {
    asm volatile("cp.async.cg.shared.global [%0], [%1], 16;" :: "r"(saddr), "l"(gptr));
}
#define CP_COMMIT() asm volatile("cp.async.commit_group;" ::: "memory")
#define CP_WAIT1()  asm volatile("cp.async.wait_group 1;" ::: "memory")

__device__ __forceinline__ void mma_tf32(float* c, const uint32_t* a, const uint32_t* b) {
    asm volatile(
        "mma.sync.aligned.m16n8k8.row.col.f32.tf32.tf32.f32 "
        "{%0,%1,%2,%3}, {%4,%5,%6,%7}, {%8,%9}, {%0,%1,%2,%3};"
        : "+f"(c[0]), "+f"(c[1]), "+f"(c[2]), "+f"(c[3])
        : "r"(a[0]), "r"(a[1]), "r"(a[2]), "r"(a[3]), "r"(b[0]), "r"(b[1]));
}

// ---------------------------------------------------------------------------
// tf32 mma GEMM: C[M,N] = A[M,K] @ Bt[N,K]^T (+bias,+resid,gelu)
// BM=BN=128, BK=32, 3-stage cp.async, 256 thr, warp tile 64x32.
// A,B K-major in smem, row stride 36 floats (pad 4) -> conflict-free frags.
// ---------------------------------------------------------------------------
#define EPI_BIAS       0
#define EPI_BIAS_RESID 1
#define EPI_BIAS_GELU  2

#define BM 128
#define BN 128
#define BKK 32
#define STAGES 3
#define ASTRIDE 36
#define A_FLOATS (BM * ASTRIDE)             // 4608
#define STAGE_FLOATS ((BM + BN) * ASTRIDE)  // 9216
#define STAGE_BYTES (STAGE_FLOATS * 4)      // 36864
#define GEMM_SMEM (STAGES * STAGE_BYTES)    // 110592

template <int EPI, bool CVT>
__global__ __launch_bounds__(256)
void tgemm_kernel(const float* __restrict__ A, const float* __restrict__ Bt,
                  const float* __restrict__ bias, const float* __restrict__ resid,
                  float* __restrict__ C, int M, int N, int K)
{
    extern __shared__ float smem[];
    const uint32_t sbase = smem_u32(smem);
    const int tid = threadIdx.x;
    const int wid = tid >> 5;
    const int lid = tid & 31;
    const int gid = lid >> 2;       // 0..7
    const int tig = lid & 3;        // 0..3
    const int wRow = (wid & 1) * 64;
    const int wCol = (wid >> 1) * 32;
    const int rowBase = blockIdx.y * BM;
    const int colBase = blockIdx.x * BN;
    const int nk = K / BKK;

    // chunk j -> stage j % 3
    auto load_stage = [&](int j) {
        const int s = j % STAGES;
        const uint32_t st = sbase + s * STAGE_BYTES;
        const int k0 = j * BKK;
        #pragma unroll
        for (int it = 0; it < 4; it++) {
            int idx = it * 256 + tid;        // 0..1023
            int r  = idx >> 3;               // 0..127
            int c4 = (idx & 7) * 4;          // 0..28
            cp_async16(st + (uint32_t)(r * ASTRIDE + c4) * 4,
                       A + (size_t)(rowBase + r) * K + k0 + c4);
        }
        #pragma unroll
        for (int it = 0; it < 4; it++) {
            int idx = it * 256 + tid;
            int r  = idx >> 3;
            int c4 = (idx & 7) * 4;
            cp_async16(st + (uint32_t)(A_FLOATS + r * ASTRIDE + c4) * 4,
                       Bt + (size_t)(colBase + r) * K + k0 + c4);
        }
    };

    float acc[4][4][4];
    #pragma unroll
    for (int mf = 0; mf < 4; mf++)
        #pragma unroll
        for (int nf = 0; nf < 4; nf++)
            #pragma unroll
            for (int r = 0; r < 4; r++) acc[mf][nf][r] = 0.0f;

    // prologue: stages 0,1
    load_stage(0); CP_COMMIT();
    load_stage(1); CP_COMMIT();

    for (int j = 0; j < nk; j++) {
        CP_WAIT1();                 // chunk j landed
        __syncthreads();            // also: everyone done computing chunk j-1

        if (j + 2 < nk) load_stage(j + 2);
        CP_COMMIT();                // committed every iter (may be empty)

        const float* As = smem + (j % STAGES) * STAGE_FLOATS;
        const float* Bs = As + A_FLOATS;

        #pragma unroll
        for (int kk = 0; kk < 4; kk++) {
            const int kb = kk * 8;
            uint32_t a[4][4], b[4][2];
            #pragma unroll
            for (int mf = 0; mf < 4; mf++) {
                const int r0 = wRow + mf * 16 + gid;
                a[mf][0] = __float_as_uint(As[r0 * ASTRIDE + kb + tig]);
                a[mf][1] = __float_as_uint(As[(r0 + 8) * ASTRIDE + kb + tig]);
                a[mf][2] = __float_as_uint(As[r0 * ASTRIDE + kb + tig + 4]);
                a[mf][3] = __float_as_uint(As[(r0 + 8) * ASTRIDE + kb + tig + 4]);
            }
            #pragma unroll
            for (int nf = 0; nf < 4; nf++) {
                const int n0 = wCol + nf * 8 + gid;
                b[nf][0] = __float_as_uint(Bs[n0 * ASTRIDE + kb + tig]);
                b[nf][1] = __float_as_uint(Bs[n0 * ASTRIDE + kb + tig + 4]);
            }
            #pragma unroll
            for (int mf = 0; mf < 4; mf++)
                #pragma unroll
                for (int nf = 0; nf < 4; nf++)
                    mma_tf32(acc[mf][nf], a[mf], b[nf]);
        }
    }

    // Epilogue: c0,c1 -> (row, col..col+1); c2,c3 -> (row+8, ...)
    #pragma unroll
    for (int mf = 0; mf < 4; mf++) {
        const int r0 = rowBase + wRow + mf * 16 + gid;
        #pragma unroll
        for (int nf = 0; nf < 4; nf++) {
            const int c = colBase + wCol + nf * 8 + tig * 2;
            const float2 bb = *reinterpret_cast<const float2*>(bias + c);
            float v0 = acc[mf][nf][0] + bb.x;
            float v1 = acc[mf][nf][1] + bb.y;
            float v2 = acc[mf][nf][2] + bb.x;
            float v3 = acc[mf][nf][3] + bb.y;
            if (EPI == EPI_BIAS_GELU) {
                v0 = 0.5f * v0 * (1.0f + erff(v0 * 0.70710678118654752f));
                v1 = 0.5f * v1 * (1.0f + erff(v1 * 0.70710678118654752f));
                v2 = 0.5f * v2 * (1.0f + erff(v2 * 0.70710678118654752f));
                v3 = 0.5f * v3 * (1.0f + erff(v3 * 0.70710678118654752f));
            }
            if (EPI == EPI_BIAS_RESID) {
                const float2 ra = *reinterpret_cast<const float2*>(
                    resid + (size_t)r0 * N + c);
                const float2 rb = *reinterpret_cast<const float2*>(
                    resid + (size_t)(r0 + 8) * N + c);
                v0 += ra.x; v1 += ra.y; v2 += rb.x; v3 += rb.y;
            }
            if (CVT) { v0 = tf32r(v0); v1 = tf32r(v1); v2 = tf32r(v2); v3 = tf32r(v3); }
            float2 o0 = {v0, v1}, o1 = {v2, v3};
            *reinterpret_cast<float2*>(C + (size_t)r0 * N + c) = o0;
            *reinterpret_cast<float2*>(C + (size_t)(r0 + 8) * N + c) = o1;
        }
    }
}

// ---------------------------------------------------------------------------
// Weight transpose + tf32 RN round: W[K,N] -> Wt[N,K]
// ---------------------------------------------------------------------------
__global__ void wt_kernel(const float* __restrict__ W, float* __restrict__ Wt,
                          int K, int N)
{
    __shared__ float t[32][33];
    int n0 = blockIdx.x * 32, k0 = blockIdx.y * 32;
    int tx = threadIdx.x, ty = threadIdx.y;  // (32, 8)
    #pragma unroll
    for (int i = 0; i < 32; i += 8)
        t[ty + i][tx] = W[(size_t)(k0 + ty + i) * N + n0 + tx];
    __syncthreads();
    #pragma unroll
    for (int i = 0; i < 32; i += 8)
        Wt[(size_t)(n0 + ty + i) * K + k0 + tx] = tf32r(t[tx][ty + i]);
}

// ---------------------------------------------------------------------------
// LayerNorm (tf32-rounded output)
// ---------------------------------------------------------------------------
__global__ void ln_kernel(const float* __restrict__ x,
                          const float* __restrict__ g,
                          const float* __restrict__ b,
                          float* __restrict__ out)
{
    int row = blockIdx.x;
    int tid = threadIdx.x;
    float v = x[row * EMBED + tid];
    float s = v, sq = v * v;
    #pragma unroll
    for (int m = 16; m; m >>= 1) {
        s  += __shfl_xor_sync(0xffffffffu, s,  m);
        sq += __shfl_xor_sync(0xffffffffu, sq, m);
    }
    __shared__ float ss[12], ssq[12];
    int w = tid >> 5, l = tid & 31;
    if (l == 0) { ss[w] = s; ssq[w] = sq; }
    __syncthreads();
    if (w == 0) {
        float a  = (l < 12) ? ss[l]  : 0.0f;
        float aq = (l < 12) ? ssq[l] : 0.0f;
        #pragma unroll
        for (int m = 16; m; m >>= 1) {
            a  += __shfl_xor_sync(0xffffffffu, a,  m);
            aq += __shfl_xor_sync(0xffffffffu, aq, m);
        }
        if (l == 0) { ss[0] = a; ssq[0] = aq; }
    }
    __syncthreads();
    float mean = ss[0] * (1.0f / EMBED);
    float var  = ssq[0] * (1.0f / EMBED) - mean * mean;
    float inv  = rsqrtf(var + 1e-5f);
    out[row * EMBED + tid] = tf32r((v - mean) * inv * g[tid] + b[tid]);
}

// ---------------------------------------------------------------------------
// Flash attention (fp32), ctx tf32-rounded
// ---------------------------------------------------------------------------
__global__ __launch_bounds__(128)
void attn_kernel(const float* __restrict__ qkv, float* __restrict__ ctx)
{
    __shared__ float Qs[64 * 64];
    __shared__ float KP[64 * 64];
    __shared__ float Vs[64 * 64];

    int tid = threadIdx.x;
    int rg = tid >> 4;
    int cg = tid & 15;
    int qt = blockIdx.x;
    int bh = blockIdx.y;
    int b  = bh / HEADS;
    int h  = bh % HEADS;

    const size_t tokBase = (size_t)b * 1024;
    const int qOff = h * HEAD_DIM;
    const int kOff = EMBED + h * HEAD_DIM;
    const int vOff = 2 * EMBED + h * HEAD_DIM;

    #pragma unroll
    for (int it = 0; it < 8; it++) {
        int lin = it * 128 + tid;
        int r = lin >> 4;
        int c4 = (lin & 15) * 4;
        float4 q = *reinterpret_cast<const float4*>(
            qkv + (tokBase + qt * 64 + r) * QKVN + qOff + c4);
        Qs[(c4 + 0) * 64 + r] = q.x;
        Qs[(c4 + 1) * 64 + r] = q.y;
        Qs[(c4 + 2) * 64 + r] = q.z;
        Qs[(c4 + 3) * 64 + r] = q.w;
    }

    float m[8], l[8], O[8][4];
    #pragma unroll
    for (int i = 0; i < 8; i++) {
        m[i] = -1e30f; l[i] = 0.0f;
        #pragma unroll
        for (int c = 0; c < 4; c++) O[i][c] = 0.0f;
    }

    for (int t = 0; t < 16; t++) {
        __syncthreads();
        #pragma unroll
        for (int it = 0; it < 8; it++) {
            int lin = it * 128 + tid;
            int r = lin >> 4;
            int c4 = (lin & 15) * 4;
            const float* rowp = qkv + (tokBase + t * 64 + r) * QKVN;
            float4 kv = *reinterpret_cast<const float4*>(rowp + kOff + c4);
            KP[(c4 + 0) * 64 + r] = kv.x;
            KP[(c4 + 1) * 64 + r] = kv.y;
            KP[(c4 + 2) * 64 + r] = kv.z;
            KP[(c4 + 3) * 64 + r] = kv.w;
            float4 vv = *reinterpret_cast<const float4*>(rowp + vOff + c4);
            *reinterpret_cast<float4*>(&Vs[r * 64 + c4]) = vv;
        }
        __syncthreads();

        float s[8][4] = {};
        #pragma unroll 4
        for (int k = 0; k < 64; k++) {
            float rq[8], rk[4];
            #pragma unroll
            for (int i = 0; i < 8; i++) rq[i] = Qs[k * 64 + rg * 8 + i];
            #pragma unroll
            for (int j = 0; j < 4; j++) rk[j] = KP[k * 64 + cg * 4 + j];
            #pragma unroll
            for (int i = 0; i < 8; i++)
                #pragma unroll
                for (int j = 0; j < 4; j++)
                    s[i][j] += rq[i] * rk[j];
        }

        #pragma unroll
        for (int i = 0; i < 8; i++) {
            float mt = -1e30f;
            #pragma unroll
            for (int j = 0; j < 4; j++) {
                s[i][j] *= 0.125f;
                mt = fmaxf(mt, s[i][j]);
            }
            #pragma unroll
            for (int mm = 8; mm; mm >>= 1)
                mt = fmaxf(mt, __shfl_xor_sync(0xffffffffu, mt, mm));
            float mn = fmaxf(m[i], mt);
            float al = __expf(m[i] - mn);
            m[i] = mn;
            float ps = 0.0f;
            #pragma unroll
            for (int j = 0; j < 4; j++) {
                s[i][j] = __expf(s[i][j] - mn);
                ps += s[i][j];
            }
            #pragma unroll
            for (int mm = 8; mm; mm >>= 1)
                ps += __shfl_xor_sync(0xffffffffu, ps, mm);
            l[i] = l[i] * al + ps;
            #pragma unroll
            for (int c = 0; c < 4; c++) O[i][c] *= al;
        }

        __syncthreads();
        #pragma unroll
        for (int i = 0; i < 8; i++)
            #pragma unroll
            for (int j = 0; j < 4; j++)
                KP[(rg * 8 + i) * 64 + cg * 4 + j] = s[i][j];
        __syncthreads();

        #pragma unroll 4
        for (int j = 0; j < 64; j++) {
            float rp[8], rv[4];
            #pragma unroll
            for (int i = 0; i < 8; i++) rp[i] = KP[(rg * 8 + i) * 64 + j];
            #pragma unroll
            for (int c = 0; c < 4; c++) rv[c] = Vs[j * 64 + cg * 4 + c];
            #pragma unroll
            for (int i = 0; i < 8; i++)
                #pragma unroll
                for (int c = 0; c < 4; c++)
                    O[i][c] += rp[i] * rv[c];
        }
    }

    #pragma unroll
    for (int i = 0; i < 8; i++) {
        float inv = 1.0f / l[i];
        size_t row = tokBase + qt * 64 + rg * 8 + i;
        float4 o;
        o.x = tf32r(O[i][0] * inv); o.y = tf32r(O[i][1] * inv);
        o.z = tf32r(O[i][2] * inv); o.w = tf32r(O[i][3] * inv);
        *reinterpret_cast<float4*>(ctx + row * EMBED + h * HEAD_DIM + cg * 4) = o;
    }
}

// ---------------------------------------------------------------------------
// Launch
// ---------------------------------------------------------------------------
extern "C" void kernel_launch(void* const* d_in, const int* in_sizes, int n_in,
                              void* d_out, int out_size)
{
    const float* x      = (const float*)d_in[0];
    const float* n1g    = (const float*)d_in[1];
    const float* n1b    = (const float*)d_in[2];
    const float* qkv_w  = (const float*)d_in[3];
    const float* qkv_b  = (const float*)d_in[4];
    const float* proj_w = (const float*)d_in[5];
    const float* proj_b = (const float*)d_in[6];
    const float* n2g    = (const float*)d_in[7];
    const float* n2b    = (const float*)d_in[8];
    const float* fc1_w  = (const float*)d_in[9];
    const float* fc1_b  = (const float*)d_in[10];
    const float* fc2_w  = (const float*)d_in[11];
    const float* fc2_b  = (const float*)d_in[12];
    float* out = (float*)d_out;

    float *h, *qkv, *ctx, *x1, *mlp, *wt;
    cudaGetSymbolAddress((void**)&h,   g_h);
    cudaGetSymbolAddress((void**)&qkv, g_qkv);
    cudaGetSymbolAddress((void**)&ctx, g_ctx);
    cudaGetSymbolAddress((void**)&x1,  g_x1);
    cudaGetSymbolAddress((void**)&mlp, g_mlp);
    cudaGetSymbolAddress((void**)&wt,  g_wt);

    float* wt_qkv  = wt;
    float* wt_proj = wt_qkv + QKVN * EMBED;
    float* wt_fc1  = wt_proj + EMBED * EMBED;
    float* wt_fc2  = wt_fc1 + MLPHID * EMBED;

    cudaFuncSetAttribute(tgemm_kernel<EPI_BIAS, false>,
                         cudaFuncAttributeMaxDynamicSharedMemorySize, GEMM_SMEM);
    cudaFuncSetAttribute(tgemm_kernel<EPI_BIAS_RESID, false>,
                         cudaFuncAttributeMaxDynamicSharedMemorySize, GEMM_SMEM);
    cudaFuncSetAttribute(tgemm_kernel<EPI_BIAS_GELU, true>,
                         cudaFuncAttributeMaxDynamicSharedMemorySize, GEMM_SMEM);

    dim3 tb(32, 8);
    wt_kernel<<<dim3(QKVN / 32,  EMBED / 32),  tb>>>(qkv_w,  wt_qkv,  EMBED,  QKVN);
    wt_kernel<<<dim3(EMBED / 32, EMBED / 32),  tb>>>(proj_w, wt_proj, EMBED,  EMBED);
    wt_kernel<<<dim3(MLPHID / 32, EMBED / 32), tb>>>(fc1_w,  wt_fc1,  EMBED,  MLPHID);
    wt_kernel<<<dim3(EMBED / 32, MLPHID / 32), tb>>>(fc2_w,  wt_fc2,  MLPHID, EMBED);

    // 1) h = LN1(x)
    ln_kernel<<<NTOK, EMBED>>>(x, n1g, n1b, h);

    // 2) qkv = h @ qkv_w + qkv_b
    tgemm_kernel<EPI_BIAS, false><<<dim3(QKVN / 128, NTOK / 128), 256, GEMM_SMEM>>>(
        h, wt_qkv, qkv_b, nullptr, qkv, NTOK, QKVN, EMBED);

    // 3) attention -> ctx
    attn_kernel<<<dim3(16, 96), 128>>>(qkv, ctx);

    // 4) x1 = x + ctx @ proj_w + proj_b
    tgemm_kernel<EPI_BIAS_RESID, false><<<dim3(EMBED / 128, NTOK / 128), 256, GEMM_SMEM>>>(
        ctx, wt_proj, proj_b, x, x1, NTOK, EMBED, EMBED);

    // 5) h = LN2(x1)
    ln_kernel<<<NTOK, EMBED>>>(x1, n2g, n2b, h);

    // 6) mlp = gelu(h @ fc1_w + fc1_b)
    tgemm_kernel<EPI_BIAS_GELU, true><<<dim3(MLPHID / 128, NTOK / 128), 256, GEMM_SMEM>>>(
        h, wt_fc1, fc1_b, nullptr, mlp, NTOK, MLPHID, EMBED);

    // 7) out = x1 + mlp @ fc2_w + fc2_b
    tgemm_kernel<EPI_BIAS_RESID, false><<<dim3(EMBED / 128, NTOK / 128), 256, GEMM_SMEM>>>(
        mlp, wt_fc2, fc2_b, x1, out, NTOK, EMBED, MLPHID);
}

// round 5
// speedup vs baseline: 3.2614x; 1.7754x over previous
#include <cuda_runtime.h>
#include <cstdint>
#include <math.h>

// ---------------------------------------------------------------------------
// TransformerBlock: B=16, N=1024, C=384, H=6, D=64, HID=1536
// Round 5 (= Round 4 resubmit after infra failure):
// tf32 mma GEMMs (swizzled smem, occ 2) + tf32 mma flash attention.
// ---------------------------------------------------------------------------

#define NTOK   16384
#define EMBED  384
#define HEADS  6
#define HEAD_DIM 64
#define MLPHID 1536
#define QKVN   1152

__device__ float g_h   [NTOK * EMBED];
__device__ float g_qkv [NTOK * QKVN];
__device__ float g_ctx [NTOK * EMBED];
__device__ float g_x1  [NTOK * EMBED];
__device__ float g_mlp [NTOK * MLPHID];
__device__ float g_wt  [QKVN*EMBED + EMBED*EMBED + MLPHID*EMBED + EMBED*MLPHID];

// ---------------------------------------------------------------------------
__device__ __forceinline__ float tf32r(float x) {
    uint32_t u;
    asm("cvt.rna.tf32.f32 %0, %1;" : "=r"(u) : "f"(x));
    return __uint_as_float(u);
}
__device__ __forceinline__ void cp_async16(uint32_t saddr, const void* gptr) {
    asm volatile("cp.async.cg.shared.global [%0], [%1], 16;" :: "r"(saddr), "l"(gptr));
}
#define CP_COMMIT() asm volatile("cp.async.commit_group;" ::: "memory")
#define CP_WAIT1()  asm volatile("cp.async.wait_group 1;" ::: "memory")

__device__ __forceinline__ uint32_t smem_u32(const void* p) {
    uint32_t a;
    asm("{ .reg .u64 t; cvta.to.shared.u64 t, %1; cvt.u32.u64 %0, t; }" : "=r"(a) : "l"(p));
    return a;
}

__device__ __forceinline__ void mma_tf32(float* c, const uint32_t* a, const uint32_t* b) {
    asm volatile(
        "mma.sync.aligned.m16n8k8.row.col.f32.tf32.tf32.f32 "
        "{%0,%1,%2,%3}, {%4,%5,%6,%7}, {%8,%9}, {%0,%1,%2,%3};"
        : "+f"(c[0]), "+f"(c[1]), "+f"(c[2]), "+f"(c[3])
        : "r"(a[0]), "r"(a[1]), "r"(a[2]), "r"(a[3]), "r"(b[0]), "r"(b[1]));
}

// ---------------------------------------------------------------------------
// tf32 mma GEMM: C[M,N] = A[M,K] @ Bt[N,K]^T (+bias,+resid,gelu)
// BM=BN=128, BK=32, 3-stage cp.async, 256 thr, warp tile 64x32.
// smem: 32-float rows, 16B-chunk XOR swizzle (chunk ^ (row&7)) ->
// conflict-free fragment gathers, 32KB/stage, 96KB total -> 2 CTAs/SM.
// ---------------------------------------------------------------------------
#define EPI_BIAS       0
#define EPI_BIAS_RESID 1
#define EPI_BIAS_GELU  2

#define BM 128
#define BN 128
#define BKK 32
#define STAGES 3
#define A_FLOATS (BM * BKK)                  // 4096
#define STAGE_FLOATS ((BM + BN) * BKK)       // 8192
#define STAGE_BYTES (STAGE_FLOATS * 4)       // 32768
#define GEMM_SMEM (STAGES * STAGE_BYTES)     // 98304

__device__ __forceinline__ float lds_sw(const float* base, int r, int c) {
    return base[r * 32 + ((((c >> 2) ^ (r & 7)) << 2) | (c & 3))];
}

template <int EPI, bool CVT>
__global__ __launch_bounds__(256, 2)
void tgemm_kernel(const float* __restrict__ A, const float* __restrict__ Bt,
                  const float* __restrict__ bias, const float* __restrict__ resid,
                  float* __restrict__ C, int M, int N, int K)
{
    extern __shared__ float smem[];
    const uint32_t sbase = smem_u32(smem);
    const int tid = threadIdx.x;
    const int wid = tid >> 5;
    const int lid = tid & 31;
    const int gid = lid >> 2;
    const int tig = lid & 3;
    const int wRow = (wid & 1) * 64;
    const int wCol = (wid >> 1) * 32;
    const int rowBase = blockIdx.y * BM;
    const int colBase = blockIdx.x * BN;
    const int nk = K / BKK;

    auto load_stage = [&](int j) {
        const int s = j % STAGES;
        const uint32_t st = sbase + s * STAGE_BYTES;
        const int k0 = j * BKK;
        #pragma unroll
        for (int it = 0; it < 4; it++) {
            int idx = it * 256 + tid;            // 0..1023
            int r  = idx >> 3;                   // 0..127
            int ch = idx & 7;                    // 16B chunk
            cp_async16(st + (uint32_t)(r * 128 + ((ch ^ (r & 7)) << 4)),
                       A + (size_t)(rowBase + r) * K + k0 + ch * 4);
        }
        #pragma unroll
        for (int it = 0; it < 4; it++) {
            int idx = it * 256 + tid;
            int r  = idx >> 3;
            int ch = idx & 7;
            cp_async16(st + (uint32_t)(A_FLOATS * 4 + r * 128 + ((ch ^ (r & 7)) << 4)),
                       Bt + (size_t)(colBase + r) * K + k0 + ch * 4);
        }
    };

    float acc[4][4][4];
    #pragma unroll
    for (int mf = 0; mf < 4; mf++)
        #pragma unroll
        for (int nf = 0; nf < 4; nf++)
            #pragma unroll
            for (int r = 0; r < 4; r++) acc[mf][nf][r] = 0.0f;

    load_stage(0); CP_COMMIT();
    load_stage(1); CP_COMMIT();

    for (int j = 0; j < nk; j++) {
        CP_WAIT1();
        __syncthreads();

        if (j + 2 < nk) load_stage(j + 2);
        CP_COMMIT();

        const float* As = smem + (j % STAGES) * STAGE_FLOATS;
        const float* Bs = As + A_FLOATS;

        #pragma unroll
        for (int kk = 0; kk < 4; kk++) {
            const int kb = kk * 8;
            uint32_t a[4][4], b[4][2];
            #pragma unroll
            for (int mf = 0; mf < 4; mf++) {
                const int r0 = wRow + mf * 16 + gid;
                a[mf][0] = __float_as_uint(lds_sw(As, r0,     kb + tig));
                a[mf][1] = __float_as_uint(lds_sw(As, r0 + 8, kb + tig));
                a[mf][2] = __float_as_uint(lds_sw(As, r0,     kb + tig + 4));
                a[mf][3] = __float_as_uint(lds_sw(As, r0 + 8, kb + tig + 4));
            }
            #pragma unroll
            for (int nf = 0; nf < 4; nf++) {
                const int n0 = wCol + nf * 8 + gid;
                b[nf][0] = __float_as_uint(lds_sw(Bs, n0, kb + tig));
                b[nf][1] = __float_as_uint(lds_sw(Bs, n0, kb + tig + 4));
            }
            #pragma unroll
            for (int mf = 0; mf < 4; mf++)
                #pragma unroll
                for (int nf = 0; nf < 4; nf++)
                    mma_tf32(acc[mf][nf], a[mf], b[nf]);
        }
    }

    #pragma unroll
    for (int mf = 0; mf < 4; mf++) {
        const int r0 = rowBase + wRow + mf * 16 + gid;
        #pragma unroll
        for (int nf = 0; nf < 4; nf++) {
            const int c = colBase + wCol + nf * 8 + tig * 2;
            const float2 bb = *reinterpret_cast<const float2*>(bias + c);
            float v0 = acc[mf][nf][0] + bb.x;
            float v1 = acc[mf][nf][1] + bb.y;
            float v2 = acc[mf][nf][2] + bb.x;
            float v3 = acc[mf][nf][3] + bb.y;
            if (EPI == EPI_BIAS_GELU) {
                v0 = 0.5f * v0 * (1.0f + erff(v0 * 0.70710678118654752f));
                v1 = 0.5f * v1 * (1.0f + erff(v1 * 0.70710678118654752f));
                v2 = 0.5f * v2 * (1.0f + erff(v2 * 0.70710678118654752f));
                v3 = 0.5f * v3 * (1.0f + erff(v3 * 0.70710678118654752f));
            }
            if (EPI == EPI_BIAS_RESID) {
                const float2 ra = *reinterpret_cast<const float2*>(
                    resid + (size_t)r0 * N + c);
                const float2 rb = *reinterpret_cast<const float2*>(
                    resid + (size_t)(r0 + 8) * N + c);
                v0 += ra.x; v1 += ra.y; v2 += rb.x; v3 += rb.y;
            }
            if (CVT) { v0 = tf32r(v0); v1 = tf32r(v1); v2 = tf32r(v2); v3 = tf32r(v3); }
            float2 o0 = {v0, v1}, o1 = {v2, v3};
            *reinterpret_cast<float2*>(C + (size_t)r0 * N + c) = o0;
            *reinterpret_cast<float2*>(C + (size_t)(r0 + 8) * N + c) = o1;
        }
    }
}

// ---------------------------------------------------------------------------
// Weight transpose + tf32 RN round: W[K,N] -> Wt[N,K]
// ---------------------------------------------------------------------------
__global__ void wt_kernel(const float* __restrict__ W, float* __restrict__ Wt,
                          int K, int N)
{
    __shared__ float t[32][33];
    int n0 = blockIdx.x * 32, k0 = blockIdx.y * 32;
    int tx = threadIdx.x, ty = threadIdx.y;
    #pragma unroll
    for (int i = 0; i < 32; i += 8)
        t[ty + i][tx] = W[(size_t)(k0 + ty + i) * N + n0 + tx];
    __syncthreads();
    #pragma unroll
    for (int i = 0; i < 32; i += 8)
        Wt[(size_t)(n0 + ty + i) * K + k0 + tx] = tf32r(t[tx][ty + i]);
}

// ---------------------------------------------------------------------------
// LayerNorm (tf32-rounded output)
// ---------------------------------------------------------------------------
__global__ void ln_kernel(const float* __restrict__ x,
                          const float* __restrict__ g,
                          const float* __restrict__ b,
                          float* __restrict__ out)
{
    int row = blockIdx.x;
    int tid = threadIdx.x;
    float v = x[row * EMBED + tid];
    float s = v, sq = v * v;
    #pragma unroll
    for (int m = 16; m; m >>= 1) {
        s  += __shfl_xor_sync(0xffffffffu, s,  m);
        sq += __shfl_xor_sync(0xffffffffu, sq, m);
    }
    __shared__ float ss[12], ssq[12];
    int w = tid >> 5, l = tid & 31;
    if (l == 0) { ss[w] = s; ssq[w] = sq; }
    __syncthreads();
    if (w == 0) {
        float a  = (l < 12) ? ss[l]  : 0.0f;
        float aq = (l < 12) ? ssq[l] : 0.0f;
        #pragma unroll
        for (int m = 16; m; m >>= 1) {
            a  += __shfl_xor_sync(0xffffffffu, a,  m);
            aq += __shfl_xor_sync(0xffffffffu, aq, m);
        }
        if (l == 0) { ss[0] = a; ssq[0] = aq; }
    }
    __syncthreads();
    float mean = ss[0] * (1.0f / EMBED);
    float var  = ssq[0] * (1.0f / EMBED) - mean * mean;
    float inv  = rsqrtf(var + 1e-5f);
    out[row * EMBED + tid] = tf32r((v - mean) * inv * g[tid] + b[tid]);
}

// ---------------------------------------------------------------------------
// Flash attention, tf32 mma for S=QK^T and O=PV.
// Grid (16 q-tiles, 96 b*h), 128 thr / 4 warps; warp owns 16 q rows.
// K,V kept in natural [token][dim] smem (stride 68); P per-warp smem tile.
// ---------------------------------------------------------------------------
#define ATS 68
#define ATTN_SMEM (3 * 64 * ATS * 4)    // Ks + Vs + Ps = 52224 B

__global__ __launch_bounds__(128)
void attn_kernel(const float* __restrict__ qkv, float* __restrict__ ctx)
{
    extern __shared__ float sm[];
    float* Ks = sm;                 // [64][ATS] token-major
    float* Vs = sm + 64 * ATS;      // [64][ATS] token-major
    float* Ps = sm + 2 * 64 * ATS;  // [64][ATS] q-row-major

    const int tid = threadIdx.x;
    const int w   = tid >> 5;
    const int lid = tid & 31;
    const int gid = lid >> 2;
    const int tig = lid & 3;
    const int qt = blockIdx.x;
    const int bh = blockIdx.y;
    const int b  = bh / HEADS;
    const int h  = bh % HEADS;

    const size_t tokBase = (size_t)b * 1024;
    const int qOff = h * HEAD_DIM;
    const int kOff = EMBED + h * HEAD_DIM;
    const int vOff = 2 * EMBED + h * HEAD_DIM;

    // Preload Q fragments (rows w*16+gid, +8) for all 8 k-frags
    uint32_t qa[8][4];
    {
        const float* q0 = qkv + (tokBase + qt * 64 + w * 16 + gid) * QKVN + qOff;
        const float* q1 = q0 + 8 * QKVN;
        #pragma unroll
        for (int kf = 0; kf < 8; kf++) {
            qa[kf][0] = __float_as_uint(q0[kf * 8 + tig]);
            qa[kf][1] = __float_as_uint(q1[kf * 8 + tig]);
            qa[kf][2] = __float_as_uint(q0[kf * 8 + tig + 4]);
            qa[kf][3] = __float_as_uint(q1[kf * 8 + tig + 4]);
        }
    }

    float m0 = -1e30f, m1 = -1e30f, l0 = 0.0f, l1 = 0.0f;
    float O[8][4];
    #pragma unroll
    for (int nf = 0; nf < 8; nf++)
        #pragma unroll
        for (int r = 0; r < 4; r++) O[nf][r] = 0.0f;

    for (int t = 0; t < 16; t++) {
        __syncthreads();   // prior tile's mma reads of Ks/Vs complete
        #pragma unroll
        for (int it = 0; it < 8; it++) {
            int lin = it * 128 + tid;
            int r = lin >> 4;
            int c4 = (lin & 15) * 4;
            const float* rowp = qkv + (tokBase + t * 64 + r) * QKVN;
            *reinterpret_cast<float4*>(&Ks[r * ATS + c4]) =
                *reinterpret_cast<const float4*>(rowp + kOff + c4);
            *reinterpret_cast<float4*>(&Vs[r * ATS + c4]) =
                *reinterpret_cast<const float4*>(rowp + vOff + c4);
        }
        __syncthreads();

        // S = Q @ K^T : warp computes 16x64
        float s[8][4];
        #pragma unroll
        for (int nf = 0; nf < 8; nf++)
            #pragma unroll
            for (int r = 0; r < 4; r++) s[nf][r] = 0.0f;
        #pragma unroll
        for (int kf = 0; kf < 8; kf++) {
            #pragma unroll
            for (int nf = 0; nf < 8; nf++) {
                const float* kb = Ks + (nf * 8 + gid) * ATS + kf * 8 + tig;
                uint32_t bf[2];
                bf[0] = __float_as_uint(kb[0]);
                bf[1] = __float_as_uint(kb[4]);
                mma_tf32(s[nf], qa[kf], bf);
            }
        }

        // online softmax: rows gid (c0,c1) and gid+8 (c2,c3); scale 0.125
        float mt0 = -1e30f, mt1 = -1e30f;
        #pragma unroll
        for (int nf = 0; nf < 8; nf++) {
            s[nf][0] *= 0.125f; s[nf][1] *= 0.125f;
            s[nf][2] *= 0.125f; s[nf][3] *= 0.125f;
            mt0 = fmaxf(mt0, fmaxf(s[nf][0], s[nf][1]));
            mt1 = fmaxf(mt1, fmaxf(s[nf][2], s[nf][3]));
        }
        mt0 = fmaxf(mt0, __shfl_xor_sync(0xffffffffu, mt0, 1));
        mt0 = fmaxf(mt0, __shfl_xor_sync(0xffffffffu, mt0, 2));
        mt1 = fmaxf(mt1, __shfl_xor_sync(0xffffffffu, mt1, 1));
        mt1 = fmaxf(mt1, __shfl_xor_sync(0xffffffffu, mt1, 2));
        float mn0 = fmaxf(m0, mt0), mn1 = fmaxf(m1, mt1);
        float al0 = __expf(m0 - mn0), al1 = __expf(m1 - mn1);
        m0 = mn0; m1 = mn1;
        float ps0 = 0.0f, ps1 = 0.0f;
        #pragma unroll
        for (int nf = 0; nf < 8; nf++) {
            s[nf][0] = __expf(s[nf][0] - m0);
            s[nf][1] = __expf(s[nf][1] - m0);
            s[nf][2] = __expf(s[nf][2] - m1);
            s[nf][3] = __expf(s[nf][3] - m1);
            ps0 += s[nf][0] + s[nf][1];
            ps1 += s[nf][2] + s[nf][3];
        }
        ps0 += __shfl_xor_sync(0xffffffffu, ps0, 1);
        ps0 += __shfl_xor_sync(0xffffffffu, ps0, 2);
        ps1 += __shfl_xor_sync(0xffffffffu, ps1, 1);
        ps1 += __shfl_xor_sync(0xffffffffu, ps1, 2);
        l0 = l0 * al0 + ps0;
        l1 = l1 * al1 + ps1;
        #pragma unroll
        for (int nf = 0; nf < 8; nf++) {
            O[nf][0] *= al0; O[nf][1] *= al0;
            O[nf][2] *= al1; O[nf][3] *= al1;
        }

        // write P (own warp rows only)
        {
            float* p0 = Ps + (w * 16 + gid) * ATS + 2 * tig;
            float* p1 = p0 + 8 * ATS;
            #pragma unroll
            for (int nf = 0; nf < 8; nf++) {
                p0[nf * 8]     = s[nf][0];
                p0[nf * 8 + 1] = s[nf][1];
                p1[nf * 8]     = s[nf][2];
                p1[nf * 8 + 1] = s[nf][3];
            }
        }
        __syncwarp();

        // O += P @ V : A = own-warp P rows, B = V[k=token][n=dim] gather
        #pragma unroll
        for (int kf = 0; kf < 8; kf++) {
            const float* pp = Ps + (w * 16 + gid) * ATS + kf * 8 + tig;
            uint32_t pa[4];
            pa[0] = __float_as_uint(pp[0]);
            pa[1] = __float_as_uint(pp[8 * ATS]);
            pa[2] = __float_as_uint(pp[4]);
            pa[3] = __float_as_uint(pp[8 * ATS + 4]);
            #pragma unroll
            for (int nf = 0; nf < 8; nf++) {
                const float* vb = Vs + (kf * 8 + tig) * ATS + nf * 8 + gid;
                uint32_t bf[2];
                bf[0] = __float_as_uint(vb[0]);
                bf[1] = __float_as_uint(vb[4 * ATS]);
                mma_tf32(O[nf], pa, bf);
            }
        }
    }

    // epilogue: normalize and write ctx (tf32 RN for next GEMM)
    const float inv0 = 1.0f / l0, inv1 = 1.0f / l1;
    const size_t r0 = tokBase + qt * 64 + w * 16 + gid;
    float* o0 = ctx + r0 * EMBED + h * HEAD_DIM + 2 * tig;
    float* o1 = o0 + 8 * EMBED;
    #pragma unroll
    for (int nf = 0; nf < 8; nf++) {
        float2 a, b;
        a.x = tf32r(O[nf][0] * inv0); a.y = tf32r(O[nf][1] * inv0);
        b.x = tf32r(O[nf][2] * inv1); b.y = tf32r(O[nf][3] * inv1);
        *reinterpret_cast<float2*>(o0 + nf * 8) = a;
        *reinterpret_cast<float2*>(o1 + nf * 8) = b;
    }
}

// ---------------------------------------------------------------------------
// Launch
// ---------------------------------------------------------------------------
extern "C" void kernel_launch(void* const* d_in, const int* in_sizes, int n_in,
                              void* d_out, int out_size)
{
    const float* x      = (const float*)d_in[0];
    const float* n1g    = (const float*)d_in[1];
    const float* n1b    = (const float*)d_in[2];
    const float* qkv_w  = (const float*)d_in[3];
    const float* qkv_b  = (const float*)d_in[4];
    const float* proj_w = (const float*)d_in[5];
    const float* proj_b = (const float*)d_in[6];
    const float* n2g    = (const float*)d_in[7];
    const float* n2b    = (const float*)d_in[8];
    const float* fc1_w  = (const float*)d_in[9];
    const float* fc1_b  = (const float*)d_in[10];
    const float* fc2_w  = (const float*)d_in[11];
    const float* fc2_b  = (const float*)d_in[12];
    float* out = (float*)d_out;

    float *h, *qkv, *ctx, *x1, *mlp, *wt;
    cudaGetSymbolAddress((void**)&h,   g_h);
    cudaGetSymbolAddress((void**)&qkv, g_qkv);
    cudaGetSymbolAddress((void**)&ctx, g_ctx);
    cudaGetSymbolAddress((void**)&x1,  g_x1);
    cudaGetSymbolAddress((void**)&mlp, g_mlp);
    cudaGetSymbolAddress((void**)&wt,  g_wt);

    float* wt_qkv  = wt;
    float* wt_proj = wt_qkv + QKVN * EMBED;
    float* wt_fc1  = wt_proj + EMBED * EMBED;
    float* wt_fc2  = wt_fc1 + MLPHID * EMBED;

    cudaFuncSetAttribute(tgemm_kernel<EPI_BIAS, true>,
                         cudaFuncAttributeMaxDynamicSharedMemorySize, GEMM_SMEM);
    cudaFuncSetAttribute(tgemm_kernel<EPI_BIAS_RESID, false>,
                         cudaFuncAttributeMaxDynamicSharedMemorySize, GEMM_SMEM);
    cudaFuncSetAttribute(tgemm_kernel<EPI_BIAS_GELU, true>,
                         cudaFuncAttributeMaxDynamicSharedMemorySize, GEMM_SMEM);
    cudaFuncSetAttribute(attn_kernel,
                         cudaFuncAttributeMaxDynamicSharedMemorySize, ATTN_SMEM);

    dim3 tb(32, 8);
    wt_kernel<<<dim3(QKVN / 32,  EMBED / 32),  tb>>>(qkv_w,  wt_qkv,  EMBED,  QKVN);
    wt_kernel<<<dim3(EMBED / 32, EMBED / 32),  tb>>>(proj_w, wt_proj, EMBED,  EMBED);
    wt_kernel<<<dim3(MLPHID / 32, EMBED / 32), tb>>>(fc1_w,  wt_fc1,  EMBED,  MLPHID);
    wt_kernel<<<dim3(EMBED / 32, MLPHID / 32), tb>>>(fc2_w,  wt_fc2,  MLPHID, EMBED);

    // 1) h = LN1(x)
    ln_kernel<<<NTOK, EMBED>>>(x, n1g, n1b, h);

    // 2) qkv = h @ qkv_w + qkv_b  (tf32 RN output -> lossless mma truncation)
    tgemm_kernel<EPI_BIAS, true><<<dim3(QKVN / 128, NTOK / 128), 256, GEMM_SMEM>>>(
        h, wt_qkv, qkv_b, nullptr, qkv, NTOK, QKVN, EMBED);

    // 3) attention -> ctx
    attn_kernel<<<dim3(16, 96), 128, ATTN_SMEM>>>(qkv, ctx);

    // 4) x1 = x + ctx @ proj_w + proj_b
    tgemm_kernel<EPI_BIAS_RESID, false><<<dim3(EMBED / 128, NTOK / 128), 256, GEMM_SMEM>>>(
        ctx, wt_proj, proj_b, x, x1, NTOK, EMBED, EMBED);

    // 5) h = LN2(x1)
    ln_kernel<<<NTOK, EMBED>>>(x1, n2g, n2b, h);

    // 6) mlp = gelu(h @ fc1_w + fc1_b)
    tgemm_kernel<EPI_BIAS_GELU, true><<<dim3(MLPHID / 128, NTOK / 128), 256, GEMM_SMEM>>>(
        h, wt_fc1, fc1_b, nullptr, mlp, NTOK, MLPHID, EMBED);

    // 7) out = x1 + mlp @ fc2_w + fc2_b
    tgemm_kernel<EPI_BIAS_RESID, false><<<dim3(EMBED / 128, NTOK / 128), 256, GEMM_SMEM>>>(
        mlp, wt_fc2, fc2_b, x1, out, NTOK, EMBED, MLPHID);
}

// round 6
// speedup vs baseline: 4.3333x; 1.3287x over previous
#include <cuda_runtime.h>
#include <cuda_fp16.h>
#include <cstdint>
#include <math.h>

// ---------------------------------------------------------------------------
// TransformerBlock: B=16, N=1024, C=384, H=6, D=64, HID=1536
// Round 6: fp16 m16n8k16 GEMMs (fp32 accum, fp16 == tf32 mantissa) +
// tf32 mma flash attention.
// ---------------------------------------------------------------------------

#define NTOK   16384
#define EMBED  384
#define HEADS  6
#define HEAD_DIM 64
#define MLPHID 1536
#define QKVN   1152

__device__ __half g_h   [NTOK * EMBED];     // LN outputs (fp16)
__device__ float  g_qkv [NTOK * QKVN];      // qkv (fp32, tf32-rounded)
__device__ __half g_ctx [NTOK * EMBED];     // attention out (fp16)
__device__ float  g_x1  [NTOK * EMBED];     // residual stream (fp32)
__device__ __half g_mlp [NTOK * MLPHID];    // gelu out (fp16)
__device__ __half g_wt  [QKVN*EMBED + EMBED*EMBED + MLPHID*EMBED + EMBED*MLPHID];

// ---------------------------------------------------------------------------
__device__ __forceinline__ float tf32r(float x) {
    uint32_t u;
    asm("cvt.rna.tf32.f32 %0, %1;" : "=r"(u) : "f"(x));
    return __uint_as_float(u);
}
__device__ __forceinline__ void cp_async16(uint32_t saddr, const void* gptr) {
    asm volatile("cp.async.cg.shared.global [%0], [%1], 16;" :: "r"(saddr), "l"(gptr));
}
#define CP_COMMIT() asm volatile("cp.async.commit_group;" ::: "memory")
#define CP_WAIT1()  asm volatile("cp.async.wait_group 1;" ::: "memory")

__device__ __forceinline__ uint32_t smem_u32(const void* p) {
    uint32_t a;
    asm("{ .reg .u64 t; cvta.to.shared.u64 t, %1; cvt.u32.u64 %0, t; }" : "=r"(a) : "l"(p));
    return a;
}

__device__ __forceinline__ void mma_f16(float* c, const uint32_t* a, const uint32_t* b) {
    asm volatile(
        "mma.sync.aligned.m16n8k16.row.col.f32.f16.f16.f32 "
        "{%0,%1,%2,%3}, {%4,%5,%6,%7}, {%8,%9}, {%0,%1,%2,%3};"
        : "+f"(c[0]), "+f"(c[1]), "+f"(c[2]), "+f"(c[3])
        : "r"(a[0]), "r"(a[1]), "r"(a[2]), "r"(a[3]), "r"(b[0]), "r"(b[1]));
}
__device__ __forceinline__ void mma_tf32(float* c, const uint32_t* a, const uint32_t* b) {
    asm volatile(
        "mma.sync.aligned.m16n8k8.row.col.f32.tf32.tf32.f32 "
        "{%0,%1,%2,%3}, {%4,%5,%6,%7}, {%8,%9}, {%0,%1,%2,%3};"
        : "+f"(c[0]), "+f"(c[1]), "+f"(c[2]), "+f"(c[3])
        : "r"(a[0]), "r"(a[1]), "r"(a[2]), "r"(a[3]), "r"(b[0]), "r"(b[1]));
}

// ---------------------------------------------------------------------------
// fp16 mma GEMM: C[M,N] = A[M,K] @ Bt[N,K]^T (+bias,+resid,gelu)
// BM=BN=128, BK=64 halves (128B/row), 3-stage cp.async, 256 thr,
// warp tile 64x32. 16B-chunk XOR swizzle; 32KB/stage, 96KB -> 2 CTAs/SM.
// ---------------------------------------------------------------------------
#define EPI_BIAS       0
#define EPI_BIAS_RESID 1
#define EPI_BIAS_GELU  2

#define BM 128
#define BN 128
#define BKH 64                                // K elems (halves) per chunk
#define STAGES 3
#define TILE_BYTES 16384                      // 128 rows x 128 B
#define STAGE_BYTES (2 * TILE_BYTES)          // 32768
#define GEMM_SMEM (STAGES * STAGE_BYTES)      // 98304

// load 2 consecutive halves at (row r, half-col kh) from a swizzled tile
__device__ __forceinline__ uint32_t lds_h2(const char* base, int r, int kh) {
    int byte = kh * 2;
    int sw = ((((byte >> 4) ^ (r & 7)) << 4) | (byte & 15));
    return *reinterpret_cast<const uint32_t*>(base + r * 128 + sw);
}

template <int EPI, bool CVT, bool OUT_HALF>
__global__ __launch_bounds__(256, 2)
void tgemm_kernel(const __half* __restrict__ A, const __half* __restrict__ Bt,
                  const float* __restrict__ bias, const float* __restrict__ resid,
                  void* __restrict__ Cv, int M, int N, int K)
{
    extern __shared__ char smem[];
    const uint32_t sbase = smem_u32(smem);
    const int tid = threadIdx.x;
    const int wid = tid >> 5;
    const int lid = tid & 31;
    const int gid = lid >> 2;
    const int tig = lid & 3;
    const int wRow = (wid & 1) * 64;
    const int wCol = (wid >> 1) * 32;
    const int rowBase = blockIdx.y * BM;
    const int colBase = blockIdx.x * BN;
    const int nk = K / BKH;

    auto load_stage = [&](int j) {
        const int s = j % STAGES;
        const uint32_t st = sbase + s * STAGE_BYTES;
        const int k0 = j * BKH;
        #pragma unroll
        for (int it = 0; it < 4; it++) {
            int idx = it * 256 + tid;            // 0..1023
            int r  = idx >> 3;                   // 0..127
            int ch = idx & 7;                    // 16B chunk = 8 halves
            cp_async16(st + (uint32_t)(r * 128 + ((ch ^ (r & 7)) << 4)),
                       A + (size_t)(rowBase + r) * K + k0 + ch * 8);
        }
        #pragma unroll
        for (int it = 0; it < 4; it++) {
            int idx = it * 256 + tid;
            int r  = idx >> 3;
            int ch = idx & 7;
            cp_async16(st + (uint32_t)(TILE_BYTES + r * 128 + ((ch ^ (r & 7)) << 4)),
                       Bt + (size_t)(colBase + r) * K + k0 + ch * 8);
        }
    };

    float acc[4][4][4];
    #pragma unroll
    for (int mf = 0; mf < 4; mf++)
        #pragma unroll
        for (int nf = 0; nf < 4; nf++)
            #pragma unroll
            for (int r = 0; r < 4; r++) acc[mf][nf][r] = 0.0f;

    load_stage(0); CP_COMMIT();
    load_stage(1); CP_COMMIT();

    for (int j = 0; j < nk; j++) {
        CP_WAIT1();
        __syncthreads();

        if (j + 2 < nk) load_stage(j + 2);
        CP_COMMIT();

        const char* As = smem + (j % STAGES) * STAGE_BYTES;
        const char* Bs = As + TILE_BYTES;

        #pragma unroll
        for (int ks = 0; ks < 4; ks++) {           // 4 k-steps of 16
            const int kb = ks * 16;
            uint32_t a[4][4], b[4][2];
            #pragma unroll
            for (int mf = 0; mf < 4; mf++) {
                const int r0 = wRow + mf * 16 + gid;
                a[mf][0] = lds_h2(As, r0,     kb + 2 * tig);
                a[mf][1] = lds_h2(As, r0 + 8, kb + 2 * tig);
                a[mf][2] = lds_h2(As, r0,     kb + 2 * tig + 8);
                a[mf][3] = lds_h2(As, r0 + 8, kb + 2 * tig + 8);
            }
            #pragma unroll
            for (int nf = 0; nf < 4; nf++) {
                const int n0 = wCol + nf * 8 + gid;
                b[nf][0] = lds_h2(Bs, n0, kb + 2 * tig);
                b[nf][1] = lds_h2(Bs, n0, kb + 2 * tig + 8);
            }
            #pragma unroll
            for (int mf = 0; mf < 4; mf++)
                #pragma unroll
                for (int nf = 0; nf < 4; nf++)
                    mma_f16(acc[mf][nf], a[mf], b[nf]);
        }
    }

    // Epilogue
    #pragma unroll
    for (int mf = 0; mf < 4; mf++) {
        const int r0 = rowBase + wRow + mf * 16 + gid;
        #pragma unroll
        for (int nf = 0; nf < 4; nf++) {
            const int c = colBase + wCol + nf * 8 + tig * 2;
            const float2 bb = *reinterpret_cast<const float2*>(bias + c);
            float v0 = acc[mf][nf][0] + bb.x;
            float v1 = acc[mf][nf][1] + bb.y;
            float v2 = acc[mf][nf][2] + bb.x;
            float v3 = acc[mf][nf][3] + bb.y;
            if (EPI == EPI_BIAS_GELU) {
                v0 = 0.5f * v0 * (1.0f + erff(v0 * 0.70710678118654752f));
                v1 = 0.5f * v1 * (1.0f + erff(v1 * 0.70710678118654752f));
                v2 = 0.5f * v2 * (1.0f + erff(v2 * 0.70710678118654752f));
                v3 = 0.5f * v3 * (1.0f + erff(v3 * 0.70710678118654752f));
            }
            if (EPI == EPI_BIAS_RESID) {
                const float2 ra = *reinterpret_cast<const float2*>(
                    resid + (size_t)r0 * N + c);
                const float2 rb = *reinterpret_cast<const float2*>(
                    resid + (size_t)(r0 + 8) * N + c);
                v0 += ra.x; v1 += ra.y; v2 += rb.x; v3 += rb.y;
            }
            if (OUT_HALF) {
                __half* Ch = (__half*)Cv;
                *reinterpret_cast<__half2*>(Ch + (size_t)r0 * N + c) =
                    __floats2half2_rn(v0, v1);
                *reinterpret_cast<__half2*>(Ch + (size_t)(r0 + 8) * N + c) =
                    __floats2half2_rn(v2, v3);
            } else {
                if (CVT) { v0 = tf32r(v0); v1 = tf32r(v1); v2 = tf32r(v2); v3 = tf32r(v3); }
                float* Cf = (float*)Cv;
                float2 o0 = {v0, v1}, o1 = {v2, v3};
                *reinterpret_cast<float2*>(Cf + (size_t)r0 * N + c) = o0;
                *reinterpret_cast<float2*>(Cf + (size_t)(r0 + 8) * N + c) = o1;
            }
        }
    }
}

// ---------------------------------------------------------------------------
// Weight transpose + fp16 RN round: W[K,N] -> Wt[N,K] (__half)
// ---------------------------------------------------------------------------
__global__ void wt_kernel(const float* __restrict__ W, __half* __restrict__ Wt,
                          int K, int N)
{
    __shared__ float t[32][33];
    int n0 = blockIdx.x * 32, k0 = blockIdx.y * 32;
    int tx = threadIdx.x, ty = threadIdx.y;
    #pragma unroll
    for (int i = 0; i < 32; i += 8)
        t[ty + i][tx] = W[(size_t)(k0 + ty + i) * N + n0 + tx];
    __syncthreads();
    #pragma unroll
    for (int i = 0; i < 32; i += 8)
        Wt[(size_t)(n0 + ty + i) * K + k0 + tx] = __float2half_rn(t[tx][ty + i]);
}

// ---------------------------------------------------------------------------
// LayerNorm -> __half output
// ---------------------------------------------------------------------------
__global__ void ln_kernel(const float* __restrict__ x,
                          const float* __restrict__ g,
                          const float* __restrict__ b,
                          __half* __restrict__ out)
{
    int row = blockIdx.x;
    int tid = threadIdx.x;
    float v = x[row * EMBED + tid];
    float s = v, sq = v * v;
    #pragma unroll
    for (int m = 16; m; m >>= 1) {
        s  += __shfl_xor_sync(0xffffffffu, s,  m);
        sq += __shfl_xor_sync(0xffffffffu, sq, m);
    }
    __shared__ float ss[12], ssq[12];
    int w = tid >> 5, l = tid & 31;
    if (l == 0) { ss[w] = s; ssq[w] = sq; }
    __syncthreads();
    if (w == 0) {
        float a  = (l < 12) ? ss[l]  : 0.0f;
        float aq = (l < 12) ? ssq[l] : 0.0f;
        #pragma unroll
        for (int m = 16; m; m >>= 1) {
            a  += __shfl_xor_sync(0xffffffffu, a,  m);
            aq += __shfl_xor_sync(0xffffffffu, aq, m);
        }
        if (l == 0) { ss[0] = a; ssq[0] = aq; }
    }
    __syncthreads();
    float mean = ss[0] * (1.0f / EMBED);
    float var  = ssq[0] * (1.0f / EMBED) - mean * mean;
    float inv  = rsqrtf(var + 1e-5f);
    out[row * EMBED + tid] = __float2half_rn((v - mean) * inv * g[tid] + b[tid]);
}

// ---------------------------------------------------------------------------
// Flash attention, tf32 mma (fp32 qkv in), __half ctx out.
// ---------------------------------------------------------------------------
#define ATS 68
#define ATTN_SMEM (3 * 64 * ATS * 4)

__global__ __launch_bounds__(128)
void attn_kernel(const float* __restrict__ qkv, __half* __restrict__ ctx)
{
    extern __shared__ float sm[];
    float* Ks = sm;
    float* Vs = sm + 64 * ATS;
    float* Ps = sm + 2 * 64 * ATS;

    const int tid = threadIdx.x;
    const int w   = tid >> 5;
    const int lid = tid & 31;
    const int gid = lid >> 2;
    const int tig = lid & 3;
    const int qt = blockIdx.x;
    const int bh = blockIdx.y;
    const int b  = bh / HEADS;
    const int h  = bh % HEADS;

    const size_t tokBase = (size_t)b * 1024;
    const int qOff = h * HEAD_DIM;
    const int kOff = EMBED + h * HEAD_DIM;
    const int vOff = 2 * EMBED + h * HEAD_DIM;

    uint32_t qa[8][4];
    {
        const float* q0 = qkv + (tokBase + qt * 64 + w * 16 + gid) * QKVN + qOff;
        const float* q1 = q0 + 8 * QKVN;
        #pragma unroll
        for (int kf = 0; kf < 8; kf++) {
            qa[kf][0] = __float_as_uint(q0[kf * 8 + tig]);
            qa[kf][1] = __float_as_uint(q1[kf * 8 + tig]);
            qa[kf][2] = __float_as_uint(q0[kf * 8 + tig + 4]);
            qa[kf][3] = __float_as_uint(q1[kf * 8 + tig + 4]);
        }
    }

    float m0 = -1e30f, m1 = -1e30f, l0 = 0.0f, l1 = 0.0f;
    float O[8][4];
    #pragma unroll
    for (int nf = 0; nf < 8; nf++)
        #pragma unroll
        for (int r = 0; r < 4; r++) O[nf][r] = 0.0f;

    for (int t = 0; t < 16; t++) {
        __syncthreads();
        #pragma unroll
        for (int it = 0; it < 8; it++) {
            int lin = it * 128 + tid;
            int r = lin >> 4;
            int c4 = (lin & 15) * 4;
            const float* rowp = qkv + (tokBase + t * 64 + r) * QKVN;
            *reinterpret_cast<float4*>(&Ks[r * ATS + c4]) =
                *reinterpret_cast<const float4*>(rowp + kOff + c4);
            *reinterpret_cast<float4*>(&Vs[r * ATS + c4]) =
                *reinterpret_cast<const float4*>(rowp + vOff + c4);
        }
        __syncthreads();

        float s[8][4];
        #pragma unroll
        for (int nf = 0; nf < 8; nf++)
            #pragma unroll
            for (int r = 0; r < 4; r++) s[nf][r] = 0.0f;
        #pragma unroll
        for (int kf = 0; kf < 8; kf++) {
            #pragma unroll
            for (int nf = 0; nf < 8; nf++) {
                const float* kb = Ks + (nf * 8 + gid) * ATS + kf * 8 + tig;
                uint32_t bf[2];
                bf[0] = __float_as_uint(kb[0]);
                bf[1] = __float_as_uint(kb[4]);
                mma_tf32(s[nf], qa[kf], bf);
            }
        }

        float mt0 = -1e30f, mt1 = -1e30f;
        #pragma unroll
        for (int nf = 0; nf < 8; nf++) {
            s[nf][0] *= 0.125f; s[nf][1] *= 0.125f;
            s[nf][2] *= 0.125f; s[nf][3] *= 0.125f;
            mt0 = fmaxf(mt0, fmaxf(s[nf][0], s[nf][1]));
            mt1 = fmaxf(mt1, fmaxf(s[nf][2], s[nf][3]));
        }
        mt0 = fmaxf(mt0, __shfl_xor_sync(0xffffffffu, mt0, 1));
        mt0 = fmaxf(mt0, __shfl_xor_sync(0xffffffffu, mt0, 2));
        mt1 = fmaxf(mt1, __shfl_xor_sync(0xffffffffu, mt1, 1));
        mt1 = fmaxf(mt1, __shfl_xor_sync(0xffffffffu, mt1, 2));
        float mn0 = fmaxf(m0, mt0), mn1 = fmaxf(m1, mt1);
        float al0 = __expf(m0 - mn0), al1 = __expf(m1 - mn1);
        m0 = mn0; m1 = mn1;
        float ps0 = 0.0f, ps1 = 0.0f;
        #pragma unroll
        for (int nf = 0; nf < 8; nf++) {
            s[nf][0] = __expf(s[nf][0] - m0);
            s[nf][1] = __expf(s[nf][1] - m0);
            s[nf][2] = __expf(s[nf][2] - m1);
            s[nf][3] = __expf(s[nf][3] - m1);
            ps0 += s[nf][0] + s[nf][1];
            ps1 += s[nf][2] + s[nf][3];
        }
        ps0 += __shfl_xor_sync(0xffffffffu, ps0, 1);
        ps0 += __shfl_xor_sync(0xffffffffu, ps0, 2);
        ps1 += __shfl_xor_sync(0xffffffffu, ps1, 1);
        ps1 += __shfl_xor_sync(0xffffffffu, ps1, 2);
        l0 = l0 * al0 + ps0;
        l1 = l1 * al1 + ps1;
        #pragma unroll
        for (int nf = 0; nf < 8; nf++) {
            O[nf][0] *= al0; O[nf][1] *= al0;
            O[nf][2] *= al1; O[nf][3] *= al1;
        }

        {
            float* p0 = Ps + (w * 16 + gid) * ATS + 2 * tig;
            float* p1 = p0 + 8 * ATS;
            #pragma unroll
            for (int nf = 0; nf < 8; nf++) {
                p0[nf * 8]     = s[nf][0];
                p0[nf * 8 + 1] = s[nf][1];
                p1[nf * 8]     = s[nf][2];
                p1[nf * 8 + 1] = s[nf][3];
            }
        }
        __syncwarp();

        #pragma unroll
        for (int kf = 0; kf < 8; kf++) {
            const float* pp = Ps + (w * 16 + gid) * ATS + kf * 8 + tig;
            uint32_t pa[4];
            pa[0] = __float_as_uint(pp[0]);
            pa[1] = __float_as_uint(pp[8 * ATS]);
            pa[2] = __float_as_uint(pp[4]);
            pa[3] = __float_as_uint(pp[8 * ATS + 4]);
            #pragma unroll
            for (int nf = 0; nf < 8; nf++) {
                const float* vb = Vs + (kf * 8 + tig) * ATS + nf * 8 + gid;
                uint32_t bf[2];
                bf[0] = __float_as_uint(vb[0]);
                bf[1] = __float_as_uint(vb[4 * ATS]);
                mma_tf32(O[nf], pa, bf);
            }
        }
    }

    const float inv0 = 1.0f / l0, inv1 = 1.0f / l1;
    const size_t r0 = tokBase + qt * 64 + w * 16 + gid;
    __half* o0 = ctx + r0 * EMBED + h * HEAD_DIM + 2 * tig;
    __half* o1 = o0 + 8 * EMBED;
    #pragma unroll
    for (int nf = 0; nf < 8; nf++) {
        *reinterpret_cast<__half2*>(o0 + nf * 8) =
            __floats2half2_rn(O[nf][0] * inv0, O[nf][1] * inv0);
        *reinterpret_cast<__half2*>(o1 + nf * 8) =
            __floats2half2_rn(O[nf][2] * inv1, O[nf][3] * inv1);
    }
}

// ---------------------------------------------------------------------------
// Launch
// ---------------------------------------------------------------------------
extern "C" void kernel_launch(void* const* d_in, const int* in_sizes, int n_in,
                              void* d_out, int out_size)
{
    const float* x      = (const float*)d_in[0];
    const float* n1g    = (const float*)d_in[1];
    const float* n1b    = (const float*)d_in[2];
    const float* qkv_w  = (const float*)d_in[3];
    const float* qkv_b  = (const float*)d_in[4];
    const float* proj_w = (const float*)d_in[5];
    const float* proj_b = (const float*)d_in[6];
    const float* n2g    = (const float*)d_in[7];
    const float* n2b    = (const float*)d_in[8];
    const float* fc1_w  = (const float*)d_in[9];
    const float* fc1_b  = (const float*)d_in[10];
    const float* fc2_w  = (const float*)d_in[11];
    const float* fc2_b  = (const float*)d_in[12];
    float* out = (float*)d_out;

    __half *h, *ctx, *mlp, *wt;
    float *qkv, *x1;
    cudaGetSymbolAddress((void**)&h,   g_h);
    cudaGetSymbolAddress((void**)&qkv, g_qkv);
    cudaGetSymbolAddress((void**)&ctx, g_ctx);
    cudaGetSymbolAddress((void**)&x1,  g_x1);
    cudaGetSymbolAddress((void**)&mlp, g_mlp);
    cudaGetSymbolAddress((void**)&wt,  g_wt);

    __half* wt_qkv  = wt;
    __half* wt_proj = wt_qkv + QKVN * EMBED;
    __half* wt_fc1  = wt_proj + EMBED * EMBED;
    __half* wt_fc2  = wt_fc1 + MLPHID * EMBED;

    cudaFuncSetAttribute(tgemm_kernel<EPI_BIAS, true, false>,
                         cudaFuncAttributeMaxDynamicSharedMemorySize, GEMM_SMEM);
    cudaFuncSetAttribute(tgemm_kernel<EPI_BIAS_RESID, false, false>,
                         cudaFuncAttributeMaxDynamicSharedMemorySize, GEMM_SMEM);
    cudaFuncSetAttribute(tgemm_kernel<EPI_BIAS_GELU, false, true>,
                         cudaFuncAttributeMaxDynamicSharedMemorySize, GEMM_SMEM);
    cudaFuncSetAttribute(attn_kernel,
                         cudaFuncAttributeMaxDynamicSharedMemorySize, ATTN_SMEM);

    dim3 tb(32, 8);
    wt_kernel<<<dim3(QKVN / 32,  EMBED / 32),  tb>>>(qkv_w,  wt_qkv,  EMBED,  QKVN);
    wt_kernel<<<dim3(EMBED / 32, EMBED / 32),  tb>>>(proj_w, wt_proj, EMBED,  EMBED);
    wt_kernel<<<dim3(MLPHID / 32, EMBED / 32), tb>>>(fc1_w,  wt_fc1,  EMBED,  MLPHID);
    wt_kernel<<<dim3(EMBED / 32, MLPHID / 32), tb>>>(fc2_w,  wt_fc2,  MLPHID, EMBED);

    // 1) h = LN1(x)  (fp16)
    ln_kernel<<<NTOK, EMBED>>>(x, n1g, n1b, h);

    // 2) qkv = h @ qkv_w + qkv_b  (fp32 out, tf32-rounded for attention)
    tgemm_kernel<EPI_BIAS, true, false><<<dim3(QKVN / 128, NTOK / 128), 256, GEMM_SMEM>>>(
        h, wt_qkv, qkv_b, nullptr, qkv, NTOK, QKVN, EMBED);

    // 3) attention -> ctx (fp16)
    attn_kernel<<<dim3(16, 96), 128, ATTN_SMEM>>>(qkv, ctx);

    // 4) x1 = x + ctx @ proj_w + proj_b  (fp32)
    tgemm_kernel<EPI_BIAS_RESID, false, false><<<dim3(EMBED / 128, NTOK / 128), 256, GEMM_SMEM>>>(
        ctx, wt_proj, proj_b, x, x1, NTOK, EMBED, EMBED);

    // 5) h = LN2(x1)  (fp16)
    ln_kernel<<<NTOK, EMBED>>>(x1, n2g, n2b, h);

    // 6) mlp = gelu(h @ fc1_w + fc1_b)  (fp16)
    tgemm_kernel<EPI_BIAS_GELU, false, true><<<dim3(MLPHID / 128, NTOK / 128), 256, GEMM_SMEM>>>(
        h, wt_fc1, fc1_b, nullptr, mlp, NTOK, MLPHID, EMBED);

    // 7) out = x1 + mlp @ fc2_w + fc2_b  (fp32)
    tgemm_kernel<EPI_BIAS_RESID, false, false><<<dim3(EMBED / 128, NTOK / 128), 256, GEMM_SMEM>>>(
        mlp, wt_fc2, fc2_b, x1, out, NTOK, EMBED, MLPHID);
}